// round 17
// baseline (speedup 1.0000x reference)
#include <cuda_runtime.h>

#define TSEQ 512
#define INF  14

typedef unsigned long long ull;

__device__ __forceinline__ ull pk(float lo, float hi){
    ull r; asm("mov.b64 %0, {%1,%2};" : "=l"(r) : "f"(lo), "f"(hi)); return r;
}
__device__ __forceinline__ float2 upk(ull v){
    float2 r; asm("mov.b64 {%0,%1}, %2;" : "=f"(r.x), "=f"(r.y) : "l"(v)); return r;
}
__device__ __forceinline__ ull ffma2(ull a, ull b, ull c){
    ull d; asm("fma.rn.f32x2 %0, %1, %2, %3;" : "=l"(d) : "l"(a), "l"(b), "l"(c)); return d;
}
__device__ __forceinline__ float tanhx(float x){
    float r; asm("tanh.approx.f32 %0, %1;" : "=f"(r) : "f"(x)); return r;
}
// i/f/o rows pre-scaled by 0.5 => sigmoid(orig) = 0.5*tanh(s)+0.5
__device__ __forceinline__ float sig_ps(float s){
    return fmaf(0.5f, tanhx(s), 0.5f);
}
__device__ __forceinline__ void cpa8(unsigned saddr, const void* gsrc){
    asm volatile("cp.async.ca.shared.global [%0], [%1], 8;" :: "r"(saddr), "l"(gsrc));
}
#define CP_COMMIT() asm volatile("cp.async.commit_group;" ::: "memory")
#define CP_WAIT1()  asm volatile("cp.async.wait_group 1;"  ::: "memory")

// 8 batch elements per warp, as TWO groups of 4 (G=0: elems 0-3, G=1: elems 4-7).
// Lane = grp*8 + j handles element (bid*8 + G*4 + grp) for BOTH groups: the
// per-lane weights (rows j, j+8, j+16, j+24) are SHARED across groups.
// Phases are textually interleaved (dotA,dotB,actA,actB,...) so each group's
// ready instructions fill the other's MUFU/SHFL stall shadows (in-order issue).
// x is staged in smem via a depth-2 cp.async ring (no register double-buffer).
__global__ void lstm_forex_kernel(
    const float* __restrict__ x,
    const float* __restrict__ Wih1, const float* __restrict__ Whh1,
    const float* __restrict__ bih1, const float* __restrict__ bhh1,
    const float* __restrict__ Wih2, const float* __restrict__ Whh2,
    const float* __restrict__ bih2, const float* __restrict__ bhh2,
    const float* __restrict__ bn_gamma, const float* __restrict__ bn_beta,
    const float* __restrict__ bn_mean, const float* __restrict__ bn_var,
    const float* __restrict__ w1, const float* __restrict__ b1,
    const float* __restrict__ w2, const float* __restrict__ b2,
    float* __restrict__ out, int Bn)
{
    // [buf][elem 0..7][pair 0..6, padded to 9 for bank spread]
    __shared__ __align__(16) ull sx[2][8][9];

    const int lane = threadIdx.x & 31;
    const int j    = lane & 7;
    const int grp  = lane >> 3;
    const int base = lane & 24;
    const unsigned FULL = 0xffffffffu;

    // ---- packed per-lane weights (shared by both groups) ----
    const float gsc[4] = {0.5f, 0.5f, 1.0f, 0.5f};
    ull wxp[4][7], wh1p[4][4], wi2p[4][4], wh2p[4][4], pb1[4], pb2[4];
#pragma unroll
    for (int g = 0; g < 4; g++){
        const int row = g * 8 + j;
        const float s = gsc[g];
#pragma unroll
        for (int k = 0; k < 7; k++)
            wxp[g][k] = pk(s * Wih1[row * 14 + 2*k], s * Wih1[row * 14 + 2*k + 1]);
#pragma unroll
        for (int k = 0; k < 4; k++){
            wh1p[g][k] = pk(s * Whh1[row * 8 + 2*k], s * Whh1[row * 8 + 2*k + 1]);
            wi2p[g][k] = pk(s * Wih2[row * 8 + 2*k], s * Wih2[row * 8 + 2*k + 1]);
            wh2p[g][k] = pk(s * Whh2[row * 8 + 2*k], s * Whh2[row * 8 + 2*k + 1]);
        }
        pb1[g] = pk(s * (bih1[row] + bhh1[row]), 0.f);
        pb2[g] = pk(s * (bih2[row] + bhh2[row]), 0.f);
    }

    // ---- cp.async lane mapping: lane (elem = grp, pair = j) covers group A
    //      and (elem = 4+grp, pair = j) covers group B; j==7 lanes idle ----
    const bool cplane = (j < 7);
    const int eA = blockIdx.x * 8 + grp;
    const int eB = eA + 4;
    const int ecA = (eA < Bn) ? eA : (Bn - 1);
    const int ecB = (eB < Bn) ? eB : (Bn - 1);
    const char* gxA = (const char*)x + (size_t)ecA * (TSEQ * INF * 4) + j * 8;
    const char* gxB = (const char*)x + (size_t)ecB * (TSEQ * INF * 4) + j * 8;
    unsigned sA, sB;
    {
        unsigned s0 = (unsigned)__cvta_generic_to_shared(&sx[0][grp][j]);
        sA = s0;                  // buf0, elem grp, pair j
        sB = s0 + 4 * 72;         // buf0, elem 4+grp
    }
    const unsigned BUFSTR = 8 * 72;   // 576 bytes per buffer

    // prime: x(0) -> buf0, x(1) -> buf1
    if (cplane){ cpa8(sA, gxA); cpa8(sB, gxB); }
    CP_COMMIT();
    if (cplane){ cpa8(sA + BUFSTR, gxA + 56); cpa8(sB + BUFSTR, gxB + 56); }
    CP_COMMIT();
    gxA += 112; gxB += 112;          // -> x(2)
    CP_WAIT1();                      // x(0) complete
    __syncwarp(FULL);

    // per-group state
    ull h1p[2][4] = {{0,0,0,0},{0,0,0,0}};
    ull h2p[2][4] = {{0,0,0,0},{0,0,0,0}};
    float c1v[2] = {0.f, 0.f}, c2v[2] = {0.f, 0.f}, h2v[2] = {0.f, 0.f};

#pragma unroll 2
    for (int t = 0; t < TSEQ; t++){
        const int s = t & 1;

        // ---- phase 1: L1 full dots (LDS x, dot; temps reused across G) ----
        ull aB[2][4];
#pragma unroll
        for (int G = 0; G < 2; G++){
            const ull* row = &sx[s][G * 4 + grp][0];
            ull tx[7];
#pragma unroll
            for (int k = 0; k < 7; k++) tx[k] = row[k];
            aB[G][0] = pb1[0]; aB[G][1] = pb1[1];
            aB[G][2] = pb1[2]; aB[G][3] = pb1[3];
#pragma unroll
            for (int k = 0; k < 4; k++){
                aB[G][0] = ffma2(wh1p[0][k], h1p[G][k], aB[G][0]);
                aB[G][1] = ffma2(wh1p[1][k], h1p[G][k], aB[G][1]);
                aB[G][2] = ffma2(wh1p[2][k], h1p[G][k], aB[G][2]);
                aB[G][3] = ffma2(wh1p[3][k], h1p[G][k], aB[G][3]);
            }
#pragma unroll
            for (int k = 0; k < 7; k++){
                aB[G][0] = ffma2(wxp[0][k], tx[k], aB[G][0]);
                aB[G][1] = ffma2(wxp[1][k], tx[k], aB[G][1]);
                aB[G][2] = ffma2(wxp[2][k], tx[k], aB[G][2]);
                aB[G][3] = ffma2(wxp[3][k], tx[k], aB[G][3]);
            }
        }
        // ---- prefetch x(t+2) into buf s (all LDS above already issued) ----
        if (t + 2 < TSEQ && cplane){
            const unsigned off = s * BUFSTR;
            cpa8(sA + off, gxA);
            cpa8(sB + off, gxB);
        }
        CP_COMMIT();
        gxA += 56; gxB += 56;

        // ---- phase 2: L1 activations (A's stalls filled by B's issue) ----
        float h1v[2];
#pragma unroll
        for (int G = 0; G < 2; G++){
            const float2 u0 = upk(aB[G][0]), u1 = upk(aB[G][1]);
            const float2 u2 = upk(aB[G][2]), u3 = upk(aB[G][3]);
            const float ai = sig_ps(u0.x + u0.y);
            const float af = sig_ps(u1.x + u1.y);
            const float ag = tanhx(u2.x + u2.y);
            const float ao = sig_ps(u3.x + u3.y);
            c1v[G] = fmaf(af, c1v[G], ai * ag);
            h1v[G] = ao * tanhx(c1v[G]);
        }
        // ---- phase 3: shuffle h1 pairs (A and B interleave) ----
#pragma unroll
        for (int G = 0; G < 2; G++){
#pragma unroll
            for (int k = 0; k < 4; k++){
                const float ha = __shfl_sync(FULL, h1v[G], base + 2*k);
                const float hb = __shfl_sync(FULL, h1v[G], base + 2*k + 1);
                h1p[G][k] = pk(ha, hb);
            }
        }
        // ---- phase 4: L2 dots ----
        ull aA[2][4];
#pragma unroll
        for (int G = 0; G < 2; G++){
            aA[G][0] = pb2[0]; aA[G][1] = pb2[1];
            aA[G][2] = pb2[2]; aA[G][3] = pb2[3];
#pragma unroll
            for (int k = 0; k < 4; k++){
                aA[G][0] = ffma2(wh2p[0][k], h2p[G][k], aA[G][0]);
                aA[G][1] = ffma2(wh2p[1][k], h2p[G][k], aA[G][1]);
                aA[G][2] = ffma2(wh2p[2][k], h2p[G][k], aA[G][2]);
                aA[G][3] = ffma2(wh2p[3][k], h2p[G][k], aA[G][3]);
            }
#pragma unroll
            for (int k = 0; k < 4; k++){
                aA[G][0] = ffma2(wi2p[0][k], h1p[G][k], aA[G][0]);
                aA[G][1] = ffma2(wi2p[1][k], h1p[G][k], aA[G][1]);
                aA[G][2] = ffma2(wi2p[2][k], h1p[G][k], aA[G][2]);
                aA[G][3] = ffma2(wi2p[3][k], h1p[G][k], aA[G][3]);
            }
        }
        // ---- phase 5: L2 activations ----
#pragma unroll
        for (int G = 0; G < 2; G++){
            const float2 u0 = upk(aA[G][0]), u1 = upk(aA[G][1]);
            const float2 u2 = upk(aA[G][2]), u3 = upk(aA[G][3]);
            const float ai = sig_ps(u0.x + u0.y);
            const float af = sig_ps(u1.x + u1.y);
            const float ag = tanhx(u2.x + u2.y);
            const float ao = sig_ps(u3.x + u3.y);
            c2v[G] = fmaf(af, c2v[G], ai * ag);
            h2v[G] = ao * tanhx(c2v[G]);
        }
        // ---- phase 6: shuffle h2 pairs ----
#pragma unroll
        for (int G = 0; G < 2; G++){
#pragma unroll
            for (int k = 0; k < 4; k++){
                const float ha = __shfl_sync(FULL, h2v[G], base + 2*k);
                const float hb = __shfl_sync(FULL, h2v[G], base + 2*k + 1);
                h2p[G][k] = pk(ha, hb);
            }
        }
        // ---- phase 7: x(t+1) guaranteed ready for next iteration ----
        CP_WAIT1();
        __syncwarp(FULL);
    }

    // ---------------- epilogue: BatchNorm (eval) + MLP head, per group ----------------
    const float scale = bn_gamma[j] * rsqrtf(bn_var[j] + 1e-5f);
#pragma unroll
    for (int G = 0; G < 2; G++){
        const float nrm = fmaf(h2v[G] - bn_mean[j], scale, bn_beta[j]);
        float p0 = w1[0 * 8 + j] * nrm;
        float p1 = w1[1 * 8 + j] * nrm;
        float p2 = w1[2 * 8 + j] * nrm;
        float p3 = w1[3 * 8 + j] * nrm;
#pragma unroll
        for (int off = 4; off > 0; off >>= 1){
            p0 += __shfl_xor_sync(FULL, p0, off);
            p1 += __shfl_xor_sync(FULL, p1, off);
            p2 += __shfl_xor_sync(FULL, p2, off);
            p3 += __shfl_xor_sync(FULL, p3, off);
        }
        const int e = blockIdx.x * 8 + G * 4 + grp;
        if (e < Bn && j == 0){
            float o = b2[0];
            o = fmaf(w2[0], fmaxf(p0 + b1[0], 0.f), o);
            o = fmaf(w2[1], fmaxf(p1 + b1[1], 0.f), o);
            o = fmaf(w2[2], fmaxf(p2 + b1[2], 0.f), o);
            o = fmaf(w2[3], fmaxf(p3 + b1[3], 0.f), o);
            out[e] = o;
        }
    }
}

extern "C" void kernel_launch(void* const* d_in, const int* in_sizes, int n_in,
                              void* d_out, int out_size)
{
    const float* x        = (const float*)d_in[0];
    const float* Wih1     = (const float*)d_in[1];
    const float* Whh1     = (const float*)d_in[2];
    const float* bih1     = (const float*)d_in[3];
    const float* bhh1     = (const float*)d_in[4];
    const float* Wih2     = (const float*)d_in[5];
    const float* Whh2     = (const float*)d_in[6];
    const float* bih2     = (const float*)d_in[7];
    const float* bhh2     = (const float*)d_in[8];
    const float* bn_gamma = (const float*)d_in[9];
    const float* bn_beta  = (const float*)d_in[10];
    const float* bn_mean  = (const float*)d_in[11];
    const float* bn_var   = (const float*)d_in[12];
    const float* w1       = (const float*)d_in[13];
    const float* b1       = (const float*)d_in[14];
    const float* w2       = (const float*)d_in[15];
    const float* b2       = (const float*)d_in[16];

    const int Bn = in_sizes[0] / (TSEQ * INF);
    const int grid = (Bn + 7) / 8;            // 8 batch elements per warp (2 groups of 4)

    lstm_forex_kernel<<<grid, 32>>>(x, Wih1, Whh1, bih1, bhh1,
                                    Wih2, Whh2, bih2, bhh2,
                                    bn_gamma, bn_beta, bn_mean, bn_var,
                                    w1, b1, w2, b2,
                                    (float*)d_out, Bn);
}